// round 6
// baseline (speedup 1.0000x reference)
#include <cuda_runtime.h>
#include <math_constants.h>

#define NUM_VIEW  300
#define NPAIR     150    // real view pairs
#define NPAIR_PAD 152    // padded so 4 lanes x 38 pairs divide evenly

// Paired codebook layout. Pair j (views 2j, 2j+1):
//   g_pairA[j] = bits of {x0, x1, y0, y1}
//   g_pairB[j] = bits of {z0, z1, c0, c1}   where c = -|v|^2/2
// Pad pairs (j >= 150) have c = -inf so their score is -inf (never selected).
__device__ ulonglong2 g_pairA[NPAIR_PAD];
__device__ ulonglong2 g_pairB[NPAIR_PAD];

__global__ void np_init_views_kernel() {
    int i = blockIdx.x * blockDim.x + threadIdx.x;
    if (i < NUM_VIEW) {
        // Match numpy float64 construction exactly, then cast to float32.
        double di  = (double)i;
        double zi  = (2.0 * di + 1.0) / (double)NUM_VIEW - 1.0;
        double r2  = 1.0 - zi * zi;
        if (r2 < 0.0) r2 = 0.0;
        double r   = sqrt(r2);
        const double PHI = (sqrt(5.0) - 1.0) * 0.5;
        double ang = 2.0 * di * CUDART_PI * PHI;
        double s, c;
        sincos(ang, &s, &c);
        float xf = (float)(r * c);
        float yf = (float)(r * s);
        float zf = (float)zi;
        float vv = __fadd_rn(__fadd_rn(__fmul_rn(xf, xf), __fmul_rn(yf, yf)),
                             __fmul_rn(zf, zf));
        float cf = -0.5f * vv;

        int j = i >> 1;
        int o = i & 1;
        float* fa = (float*)&g_pairA[j];
        float* fb = (float*)&g_pairB[j];
        fa[0 + o] = xf;
        fa[2 + o] = yf;
        fb[0 + o] = zf;
        fb[2 + o] = cf;
    } else if (i < 2 * (NPAIR_PAD - NPAIR) + NUM_VIEW) {
        // pad views 300..303 -> pairs 150,151: score = -inf
        int j = i >> 1;
        int o = i & 1;
        float* fa = (float*)&g_pairA[j];
        float* fb = (float*)&g_pairB[j];
        fa[0 + o] = 0.0f;
        fa[2 + o] = 0.0f;
        fb[0 + o] = 0.0f;
        fb[2 + o] = -CUDART_INF_F;
    }
}

__device__ __forceinline__ unsigned long long np_fma2(
        unsigned long long a, unsigned long long b, unsigned long long c) {
    unsigned long long d;
    asm("fma.rn.f32x2 %0, %1, %2, %3;" : "=l"(d) : "l"(a), "l"(b), "l"(c));
    return d;
}

__device__ __forceinline__ unsigned long long np_pack2(float lo, float hi) {
    unsigned long long d;
    asm("mov.b64 %0, {%1, %2};" : "=l"(d) : "f"(lo), "f"(hi));
    return d;
}

__device__ __forceinline__ void np_unpack2(float& lo, float& hi,
                                           unsigned long long v) {
    asm("mov.b64 {%0, %1}, %2;" : "=f"(lo), "=f"(hi) : "l"(v));
}

__device__ __forceinline__ void np_merge_max(float& s0, int& i0, float s1, int i1) {
    // first-max (lowest index) wins on ties — matches argmin-first semantics
    if (s1 > s0 || (s1 == s0 && i1 < i0)) { s0 = s1; i0 = i1; }
}

// 4 threads per point. Lane h in {0..3} scans pairs j = h + 4k, k in [0,38).
// argmin(|n-v|^2) == argmax(dot(n,v) - |v|^2/2): packed f32x2 FMAs.
// MODE 0: indices written as float32 (output = 13*P floats)
// MODE 1: indices written as int64 bit-pattern (output = 14*P float slots)
template <int MODE>
__global__ void __launch_bounds__(896)
np_main_kernel(const float* __restrict__ normals,
               const int*   __restrict__ idxs,
               float*       __restrict__ out,
               int N, int S, int logS, int P) {
    __shared__ ulonglong2 sA[NPAIR_PAD];
    __shared__ ulonglong2 sB[NPAIR_PAD];
    for (int i = threadIdx.x; i < NPAIR_PAD; i += blockDim.x) {
        sA[i] = g_pairA[i];
        sB[i] = g_pairB[i];
    }
    __syncthreads();

    int t = blockIdx.x * blockDim.x + threadIdx.x;
    int p = t >> 2;
    int h = t & 3;
    if (p >= P) return;

    int b   = (logS >= 0) ? (p >> logS) : (p / S);
    int idx = idxs[p];
    const float* nptr = normals + ((long long)b * N + idx) * 3;
    float nx = __ldg(nptr + 0);
    float ny = __ldg(nptr + 1);
    float nz = __ldg(nptr + 2);

    unsigned long long pnx = np_pack2(nx, nx);
    unsigned long long pny = np_pack2(ny, ny);
    unsigned long long pnz = np_pack2(nz, nz);

    // --- argmax over this lane's 38 pairs: 2 pairs / iteration, 19 iters ---
    // iteration m: pairs j0 = h + 8m, j1 = h + 8m + 4
    float bl0 = -CUDART_INF_F, bh0 = -CUDART_INF_F,
          bl1 = -CUDART_INF_F, bh1 = -CUDART_INF_F;
    int   ml0 = 0, mh0 = 0, ml1 = 0, mh1 = 0;

#pragma unroll 4
    for (int m = 0; m < 19; m++) {
        int j0 = h + 8 * m;
        ulonglong2 A0 = sA[j0],     B0 = sB[j0];
        ulonglong2 A1 = sA[j0 + 4], B1 = sB[j0 + 4];

        unsigned long long s0 = np_fma2(pnx, A0.x,
                                 np_fma2(pny, A0.y, np_fma2(pnz, B0.x, B0.y)));
        unsigned long long s1 = np_fma2(pnx, A1.x,
                                 np_fma2(pny, A1.y, np_fma2(pnz, B1.x, B1.y)));

        float f0l, f0h, f1l, f1h;
        np_unpack2(f0l, f0h, s0);
        np_unpack2(f1l, f1h, s1);

        // strict > keeps first-win; record only loop counter m (reg reuse)
        if (f0l > bl0) { bl0 = f0l; ml0 = m; }
        if (f0h > bh0) { bh0 = f0h; mh0 = m; }
        if (f1l > bl1) { bl1 = f1l; ml1 = m; }
        if (f1h > bh1) { bh1 = f1h; mh1 = m; }
    }

    // reconstruct global view indices
    int il0 = 2 * (h + 8 * ml0);
    int ih0 = 2 * (h + 8 * mh0) + 1;
    int il1 = 2 * (h + 8 * ml1 + 4);
    int ih1 = 2 * (h + 8 * mh1 + 4) + 1;

    // merge 4 accumulators (index tie-break keeps exact first-win semantics)
    np_merge_max(bl0, il0, bh0, ih0);
    np_merge_max(bl1, il1, bh1, ih1);
    np_merge_max(bl0, il0, bl1, il1);

    // butterfly merge across the 4 lanes of the point
    float os; int oi;
    os = __shfl_xor_sync(0xffffffffu, bl0, 1);
    oi = __shfl_xor_sync(0xffffffffu, il0, 1);
    np_merge_max(bl0, il0, os, oi);
    os = __shfl_xor_sync(0xffffffffu, bl0, 2);
    oi = __shfl_xor_sync(0xffffffffu, il0, 2);
    np_merge_max(bl0, il0, os, oi);
    int bi = il0;

    // --- rotation matrix from towards = -n, angle = 0 (R1 = I, rot = R2) ---
    float ax_x = -nx, ax_y = -ny, ax_z = -nz;
    float ay_x = -ax_y;   // = ny
    float ay_y =  ax_x;   // = -nx
    float ay_z = 0.0f;
    if (ay_x * ay_x + ay_y * ay_y + ay_z * ay_z == 0.0f) {
        ay_x = 0.0f; ay_y = 1.0f; ay_z = 0.0f;
    }
    float inva = 1.0f / sqrtf(ax_x * ax_x + ax_y * ax_y + ax_z * ax_z);
    ax_x *= inva; ax_y *= inva; ax_z *= inva;
    float invy = 1.0f / sqrtf(ay_x * ay_x + ay_y * ay_y + ay_z * ay_z);
    ay_x *= invy; ay_y *= invy; ay_z *= invy;
    float az_x = ax_y * ay_z - ax_z * ay_y;
    float az_y = ax_z * ay_x - ax_x * ay_z;
    float az_z = ax_x * ay_y - ax_y * ay_x;

    // --- outputs (stores split between the four lanes of the point) ---
    float* out_xyz;
    float* out_rot;
    if (MODE == 0) {
        out_xyz = out + P;
        out_rot = out + P + 3 * (long long)P;
    } else {
        out_xyz = out + 2 * (long long)P;
        out_rot = out + 2 * (long long)P + 3 * (long long)P;
    }

    long long base3 = (long long)p * 3;
    long long base9 = (long long)p * 9;

    // row-major [r][c]: col0 = ax, col1 = ay, col2 = az
    if (h == 0) {
        if (MODE == 0) {
            out[p] = (float)bi;
        } else {
            ((long long*)out)[p] = (long long)bi;
        }
        out_xyz[base3 + 0] = nx;
        out_xyz[base3 + 1] = ny;
    } else if (h == 1) {
        out_xyz[base3 + 2] = nz;
        out_rot[base9 + 0] = ax_x;
        out_rot[base9 + 1] = ay_x;
        out_rot[base9 + 2] = az_x;
    } else if (h == 2) {
        out_rot[base9 + 3] = ax_y;
        out_rot[base9 + 4] = ay_y;
        out_rot[base9 + 5] = az_y;
    } else {
        out_rot[base9 + 6] = ax_z;
        out_rot[base9 + 7] = ay_z;
        out_rot[base9 + 8] = az_z;
    }
}

extern "C" void kernel_launch(void* const* d_in, const int* in_sizes, int n_in,
                              void* d_out, int out_size) {
    const float* normals = (const float*)d_in[0];
    const int*   idxs    = (const int*)d_in[1];
    float*       out     = (float*)d_out;

    const int B = 8;
    int P = in_sizes[1];            // B*S = 32768
    int S = P / B;                  // 4096
    int N = in_sizes[0] / (B * 3);  // 500000

    int logS = -1;
    if (S > 0 && (S & (S - 1)) == 0) {
        logS = 0;
        while ((1 << logS) < S) logS++;
    }

    np_init_views_kernel<<<76, 4>>>();

    // 4 lanes per point: 131072 threads, 896/block -> 147 blocks (1 wave)
    const int threads = 896;
    long long total = 4LL * P;
    int blocks = (int)((total + threads - 1) / threads);
    if (out_size == 14 * P) {
        np_main_kernel<1><<<blocks, threads>>>(normals, idxs, out, N, S, logS, P);
    } else {
        np_main_kernel<0><<<blocks, threads>>>(normals, idxs, out, N, S, logS, P);
    }
}

// round 7
// speedup vs baseline: 1.1830x; 1.1830x over previous
#include <cuda_runtime.h>
#include <math_constants.h>

#define NUM_VIEW 300
#define NPAIR    150   // view pairs
#define WVIEW    80    // window: views scanned per point (covering-radius bound)
#define WPAIR    40    // window pairs
#define W0MAX    (NUM_VIEW - WVIEW)   // 220

// Paired codebook layout. Pair j (views 2j, 2j+1):
//   g_pairA[j] = bits of {x0, x1, y0, y1}
//   g_pairB[j] = bits of {z0, z1, c0, c1}   where c = -|v|^2/2
__device__ ulonglong2 g_pairA[NPAIR];
__device__ ulonglong2 g_pairB[NPAIR];

__global__ void np_init_views_kernel() {
    int i = blockIdx.x * blockDim.x + threadIdx.x;
    if (i < NUM_VIEW) {
        // Match numpy float64 construction exactly, then cast to float32.
        double di  = (double)i;
        double zi  = (2.0 * di + 1.0) / (double)NUM_VIEW - 1.0;
        double r2  = 1.0 - zi * zi;
        if (r2 < 0.0) r2 = 0.0;
        double r   = sqrt(r2);
        const double PHI = (sqrt(5.0) - 1.0) * 0.5;
        double ang = 2.0 * di * CUDART_PI * PHI;
        double s, c;
        sincos(ang, &s, &c);
        float xf = (float)(r * c);
        float yf = (float)(r * s);
        float zf = (float)zi;
        float vv = __fadd_rn(__fadd_rn(__fmul_rn(xf, xf), __fmul_rn(yf, yf)),
                             __fmul_rn(zf, zf));
        float cf = -0.5f * vv;

        int j = i >> 1;
        int o = i & 1;
        float* fa = (float*)&g_pairA[j];
        float* fb = (float*)&g_pairB[j];
        fa[0 + o] = xf;
        fa[2 + o] = yf;
        fb[0 + o] = zf;
        fb[2 + o] = cf;
    }
}

__device__ __forceinline__ unsigned long long np_fma2(
        unsigned long long a, unsigned long long b, unsigned long long c) {
    unsigned long long d;
    asm("fma.rn.f32x2 %0, %1, %2, %3;" : "=l"(d) : "l"(a), "l"(b), "l"(c));
    return d;
}

__device__ __forceinline__ unsigned long long np_pack2(float lo, float hi) {
    unsigned long long d;
    asm("mov.b64 %0, {%1, %2};" : "=l"(d) : "f"(lo), "f"(hi));
    return d;
}

__device__ __forceinline__ void np_unpack2(float& lo, float& hi,
                                           unsigned long long v) {
    asm("mov.b64 {%0, %1}, %2;" : "=f"(lo), "=f"(hi) : "l"(v));
}

__device__ __forceinline__ void np_merge_max(float& s0, int& i0, float s1, int i1) {
    // first-max (lowest index) wins on ties — matches argmin-first semantics
    bool g = (s1 > s0) || (s1 == s0 && i1 < i0);
    s0 = g ? s1 : s0;
    i0 = g ? i1 : i0;
}

// 2 threads per point. Views sorted by z -> winner lies within +-40 indices
// of i_c = round((u_z+1)*150). Lane h scans pairs {jp+2m+h} and {jp+20+2m+h}.
// argmin(|n-v|^2) == argmax(dot(n,v) - |v|^2/2): packed f32x2 FMAs.
// MODE 0: indices written as float32 (output = 13*P floats)
// MODE 1: indices written as int64 bit-pattern (output = 14*P float slots)
template <int MODE>
__global__ void __launch_bounds__(448)
np_main_kernel(const float* __restrict__ normals,
               const int*   __restrict__ idxs,
               float*       __restrict__ out,
               int N, int S, int logS, int P) {
    __shared__ ulonglong2 sA[NPAIR];
    __shared__ ulonglong2 sB[NPAIR];

    int t = blockIdx.x * blockDim.x + threadIdx.x;
    int p = t >> 1;
    int h = t & 1;
    int pc = (p < P) ? p : (P - 1);   // clamp (keep barrier convergent)

    // gather loads issued early — overlap with codebook preload below
    int b   = (logS >= 0) ? (pc >> logS) : (pc / S);
    int idx = idxs[pc];
    const float* nptr = normals + ((long long)b * N + idx) * 3;
    float nx = __ldg(nptr + 0);
    float ny = __ldg(nptr + 1);
    float nz = __ldg(nptr + 2);

    for (int i = threadIdx.x; i < NPAIR; i += blockDim.x) {
        sA[i] = g_pairA[i];
        sB[i] = g_pairB[i];
    }
    __syncthreads();

    // window center from normalized z (approximation fine: 1.4x margin)
    float nn  = fmaf(nx, nx, fmaf(ny, ny, nz * nz));
    float uz  = nz * rsqrtf(nn);
    int   ic  = __float2int_rn(fmaf(uz, 150.0f, 150.0f));
    int   w0  = ic - (WVIEW / 2);
    w0 = (w0 < 0) ? 0 : ((w0 > W0MAX) ? W0MAX : w0);
    w0 &= ~1;                 // even start so pairs align
    int jp = w0 >> 1;         // first window pair

    unsigned long long pnx = np_pack2(nx, nx);
    unsigned long long pny = np_pack2(ny, ny);
    unsigned long long pnz = np_pack2(nz, nz);

    // --- argmax over this lane's 20 window pairs: 2 pairs/iter, 10 iters ---
    float bAl = -CUDART_INF_F, bAh = -CUDART_INF_F,
          bBl = -CUDART_INF_F, bBh = -CUDART_INF_F;
    int   mAl = 0, mAh = 0, mBl = 0, mBh = 0;

#pragma unroll 5
    for (int m = 0; m < 10; m++) {
        int jA = jp + 2 * m + h;
        int jB = jA + 20;
        ulonglong2 A0 = sA[jA], B0 = sB[jA];
        ulonglong2 A1 = sA[jB], B1 = sB[jB];

        unsigned long long s0 = np_fma2(pnx, A0.x,
                                 np_fma2(pny, A0.y, np_fma2(pnz, B0.x, B0.y)));
        unsigned long long s1 = np_fma2(pnx, A1.x,
                                 np_fma2(pny, A1.y, np_fma2(pnz, B1.x, B1.y)));

        float f0l, f0h, f1l, f1h;
        np_unpack2(f0l, f0h, s0);
        np_unpack2(f1l, f1h, s1);

        // strict > keeps first-win; ternary form -> FSEL/SEL (4-cyc) chains
        bool gAl = f0l > bAl;  bAl = gAl ? f0l : bAl;  mAl = gAl ? m : mAl;
        bool gAh = f0h > bAh;  bAh = gAh ? f0h : bAh;  mAh = gAh ? m : mAh;
        bool gBl = f1l > bBl;  bBl = gBl ? f1l : bBl;  mBl = gBl ? m : mBl;
        bool gBh = f1h > bBh;  bBh = gBh ? f1h : bBh;  mBh = gBh ? m : mBh;
    }

    // reconstruct global view indices
    int iAl = 2 * (jp + 2 * mAl + h);
    int iAh = 2 * (jp + 2 * mAh + h) + 1;
    int iBl = 2 * (jp + 2 * mBl + h + 20);
    int iBh = 2 * (jp + 2 * mBh + h + 20) + 1;

    // merge 4 accumulators (index tie-break keeps exact first-win semantics)
    np_merge_max(bAl, iAl, bAh, iAh);
    np_merge_max(bBl, iBl, bBh, iBh);
    np_merge_max(bAl, iAl, bBl, iBl);

    // merge across the lane pair
    float os = __shfl_xor_sync(0xffffffffu, bAl, 1);
    int   oi = __shfl_xor_sync(0xffffffffu, iAl, 1);
    np_merge_max(bAl, iAl, os, oi);
    int bi = iAl;

    // --- rotation matrix from towards = -n, angle = 0 (R1 = I, rot = R2) ---
    float ax_x = -nx, ax_y = -ny, ax_z = -nz;
    float ay_x = -ax_y;   // = ny
    float ay_y =  ax_x;   // = -nx
    float ay_z = 0.0f;
    if (ay_x * ay_x + ay_y * ay_y + ay_z * ay_z == 0.0f) {
        ay_x = 0.0f; ay_y = 1.0f; ay_z = 0.0f;
    }
    float inva = 1.0f / sqrtf(ax_x * ax_x + ax_y * ax_y + ax_z * ax_z);
    ax_x *= inva; ax_y *= inva; ax_z *= inva;
    float invy = 1.0f / sqrtf(ay_x * ay_x + ay_y * ay_y + ay_z * ay_z);
    ay_x *= invy; ay_y *= invy; ay_z *= invy;
    float az_x = ax_y * ay_z - ax_z * ay_y;
    float az_y = ax_z * ay_x - ax_x * ay_z;
    float az_z = ax_x * ay_y - ax_y * ay_x;

    // --- outputs (stores split between the two lanes of the pair) ---
    if (p < P) {
        float* out_xyz;
        float* out_rot;
        if (MODE == 0) {
            out_xyz = out + P;
            out_rot = out + P + 3 * (long long)P;
        } else {
            out_xyz = out + 2 * (long long)P;
            out_rot = out + 2 * (long long)P + 3 * (long long)P;
        }

        long long base3 = (long long)p * 3;
        long long base9 = (long long)p * 9;

        if (h == 0) {
            if (MODE == 0) {
                out[p] = (float)bi;
            } else {
                ((long long*)out)[p] = (long long)bi;
            }
            out_xyz[base3 + 0] = nx;
            out_xyz[base3 + 1] = ny;
            out_xyz[base3 + 2] = nz;
            // row-major [r][c]: col0 = ax, col1 = ay, col2 = az
            out_rot[base9 + 0] = ax_x;
            out_rot[base9 + 1] = ay_x;
            out_rot[base9 + 2] = az_x;
            out_rot[base9 + 3] = ax_y;
        } else {
            out_rot[base9 + 4] = ay_y;
            out_rot[base9 + 5] = az_y;
            out_rot[base9 + 6] = ax_z;
            out_rot[base9 + 7] = ay_z;
            out_rot[base9 + 8] = az_z;
        }
    }
}

extern "C" void kernel_launch(void* const* d_in, const int* in_sizes, int n_in,
                              void* d_out, int out_size) {
    const float* normals = (const float*)d_in[0];
    const int*   idxs    = (const int*)d_in[1];
    float*       out     = (float*)d_out;

    const int B = 8;
    int P = in_sizes[1];            // B*S = 32768
    int S = P / B;                  // 4096
    int N = in_sizes[0] / (B * 3);  // 500000

    int logS = -1;
    if (S > 0 && (S & (S - 1)) == 0) {
        logS = 0;
        while ((1 << logS) < S) logS++;
    }

    np_init_views_kernel<<<75, 4>>>();

    // 2 lanes per point; one balanced wave: 147 blocks x 448 threads
    const int threads = 448;
    long long total = 2LL * P;
    int blocks = (int)((total + threads - 1) / threads);
    if (out_size == 14 * P) {
        np_main_kernel<1><<<blocks, threads>>>(normals, idxs, out, N, S, logS, P);
    } else {
        np_main_kernel<0><<<blocks, threads>>>(normals, idxs, out, N, S, logS, P);
    }
}